// round 2
// baseline (speedup 1.0000x reference)
#include <cuda_runtime.h>
#include <cstdint>

#define T_LEN 4096
#define IN_DIM 256
#define H_DIM 1024
#define G4H   4096
#define NCTA  128
#define UNITS 8     // hidden units per CTA (128 * 8 = 1024)

// ---------------- device scratch (static: no allocations allowed) ----------
__device__ float g_xz[(size_t)T_LEN * G4H];     // 64 MB: input projections for current layer
__device__ float g_hall[(size_t)T_LEN * H_DIM]; // 16 MB: h outputs of current layer
__device__ float g_h[2][H_DIM];                 // double-buffered h broadcast
__device__ int   g_flag[NCTA];                  // per-CTA monotonic step flags

__global__ void reset_kernel() {
    if (threadIdx.x < NCTA) g_flag[threadIdx.x] = 0;
}

// ---------------- memory-order helpers --------------------------------------
__device__ __forceinline__ int ld_acquire_gpu(const int* p) {
    int v;
    asm volatile("ld.acquire.gpu.global.b32 %0, [%1];" : "=r"(v) : "l"(p));
    return v;
}
__device__ __forceinline__ void st_release_gpu(int* p, int v) {
    asm volatile("st.release.gpu.global.b32 [%0], %1;" :: "l"(p), "r"(v));
}

// ---------------- packed f32x2 FMA helper ----------------------------------
union F2u { float2 f; unsigned long long u; };

__device__ __forceinline__ void fma2(unsigned long long& d,
                                     unsigned long long a,
                                     unsigned long long b) {
    asm volatile("fma.rn.f32x2 %0, %1, %2, %0;" : "+l"(d) : "l"(a), "l"(b));
}

// ---------------- fast, overflow-safe activations ---------------------------
__device__ __forceinline__ float fast_sigmoid(float x) {
    return __fdividef(1.f, 1.f + __expf(-x));
}
__device__ __forceinline__ float fast_tanh(float x) {
    float a = fabsf(x);
    float e = __expf(-2.f * a);               // in (0, 1], never overflows
    float t = (1.f - e) * __fdividef(1.f, 1.f + e);
    return copysignf(t, x);
}

// ---------------- GEMM: xz = A @ W^T + bias --------------------------------
template<int K>
__global__ __launch_bounds__(256, 2)
void gemm_xz(const float* __restrict__ A_in,
             const float* __restrict__ W,
             const float* __restrict__ bias) {
    const float* A = A_in ? A_in : g_hall;   // nullptr => previous layer's h

    __shared__ float As[16][132];
    __shared__ float Bs[16][132];

    const int tid  = threadIdx.x;
    const int row0 = blockIdx.y * 128;
    const int col0 = blockIdx.x * 128;
    const int ty   = tid >> 4;     // 0..15
    const int tx   = tid & 15;     // 0..15

    float acc[8][8];
#pragma unroll
    for (int i = 0; i < 8; i++)
#pragma unroll
        for (int j = 0; j < 8; j++) acc[i][j] = 0.f;

    for (int k0 = 0; k0 < K; k0 += 16) {
#pragma unroll
        for (int i = 0; i < 2; i++) {
            int f  = tid + i * 256;
            int r  = f >> 2;
            int c4 = f & 3;
            float4 va = *(const float4*)(A + (size_t)(row0 + r) * K + k0 + c4 * 4);
            As[c4 * 4 + 0][r] = va.x;
            As[c4 * 4 + 1][r] = va.y;
            As[c4 * 4 + 2][r] = va.z;
            As[c4 * 4 + 3][r] = va.w;
            float4 vb = *(const float4*)(W + (size_t)(col0 + r) * K + k0 + c4 * 4);
            Bs[c4 * 4 + 0][r] = vb.x;
            Bs[c4 * 4 + 1][r] = vb.y;
            Bs[c4 * 4 + 2][r] = vb.z;
            Bs[c4 * 4 + 3][r] = vb.w;
        }
        __syncthreads();

#pragma unroll
        for (int k = 0; k < 16; k++) {
            float4 a0 = *(const float4*)&As[k][ty * 8];
            float4 a1 = *(const float4*)&As[k][ty * 8 + 4];
            float4 b0 = *(const float4*)&Bs[k][tx * 8];
            float4 b1 = *(const float4*)&Bs[k][tx * 8 + 4];
            float a[8] = {a0.x, a0.y, a0.z, a0.w, a1.x, a1.y, a1.z, a1.w};
            float b[8] = {b0.x, b0.y, b0.z, b0.w, b1.x, b1.y, b1.z, b1.w};
#pragma unroll
            for (int i = 0; i < 8; i++)
#pragma unroll
                for (int j = 0; j < 8; j++) acc[i][j] += a[i] * b[j];
        }
        __syncthreads();
    }

    float bj[8];
#pragma unroll
    for (int j = 0; j < 8; j++) bj[j] = bias[col0 + tx * 8 + j];

#pragma unroll
    for (int i = 0; i < 8; i++) {
        int r = row0 + ty * 8 + i;
#pragma unroll
        for (int j = 0; j < 8; j++) {
            g_xz[(size_t)r * G4H + col0 + tx * 8 + j] = acc[i][j] + bj[j];
        }
    }
}

// ---------------- recurrent scan -------------------------------------------
// 128 CTAs x 256 threads, all co-resident. CTA b owns hidden units [8b, 8b+8).
// W_hh slice (32 rows x 1024) lives in REGISTERS (128 floats/thread).
// Sync: per-CTA monotonic flag, release-store by producer thread 0,
// acquire-load spin by consumer threads 0..127 (one flag each).
__global__ __launch_bounds__(256, 1)
void lstm_scan(const float* __restrict__ Whh, int layer) {
    __shared__ float sh_h[H_DIM];
    __shared__ float sh_z[32];
    __shared__ float sh_hout[8];

    const int bid   = blockIdx.x;
    const int tid   = threadIdx.x;
    const int wid   = tid >> 5;
    const int lane  = tid & 31;
    const int ubase = bid * UNITS;

    // load this CTA's W_hh slice into registers.
    // warp w handles slice-rows s = 4w..4w+3, s -> (gate = s>>3, unit = s&7).
    // lane covers columns c*128 + lane*4 .. +3 for c = 0..7.
    float4 wreg[4][8];
#pragma unroll
    for (int j = 0; j < 4; j++) {
        int s    = wid * 4 + j;
        int gate = s >> 3;
        int unit = s & 7;
        const float4* wr =
            (const float4*)(Whh + ((size_t)gate * H_DIM + ubase + unit) * H_DIM);
#pragma unroll
        for (int c = 0; c < 8; c++) wreg[j][c] = wr[c * 32 + lane];
    }

    const int base = layer * (T_LEN + 1) + 1;   // strictly > previous layer's max flag
    float c_state = 0.f;                        // meaningful for tid < 8 only

    // init publish: h_{-1} = 0 lives in parity-1 buffer
    if (tid == 0) {
        float4 z4 = make_float4(0.f, 0.f, 0.f, 0.f);
        __stcg((float4*)&g_h[1][ubase], z4);
        __stcg((float4*)&g_h[1][ubase + 4], z4);
        st_release_gpu(&g_flag[bid], base);     // flag >= base + 0  => h_{-1} ready
    }

    for (int t = 0; t < T_LEN; t++) {
        // prefetch xz for this step (independent of h)
        float xzi = 0.f, xzf = 0.f, xzg = 0.f, xzo = 0.f;
        if (tid < UNITS) {
            const float* xz = g_xz + (size_t)t * G4H + ubase + tid;
            xzi = __ldg(xz);
            xzf = __ldg(xz + H_DIM);
            xzg = __ldg(xz + 2 * H_DIM);
            xzo = __ldg(xz + 3 * H_DIM);
        }

        // wait for all 128 producer flags: thread i owns flag i
        if (tid < NCTA) {
            while (ld_acquire_gpu(&g_flag[tid]) < base + t) { }
        }
        __syncthreads();

        // broadcast h_{t-1} into shared (256 x float4 = 4KB)
        {
            const float4* hp = (const float4*)g_h[(t + 1) & 1];
            ((float4*)sh_h)[tid] = __ldcg(hp + tid);
        }
        __syncthreads();

        // packed dot products: 4 rows per warp, 32 cols per lane (conflict-free)
        unsigned long long acc[4];
        {
            F2u z; z.f = make_float2(0.f, 0.f);
            acc[0] = acc[1] = acc[2] = acc[3] = z.u;
        }
#pragma unroll
        for (int c = 0; c < 8; c++) {
            float4 hv = ((const float4*)sh_h)[c * 32 + lane];
            F2u hlo, hhi;
            hlo.f = make_float2(hv.x, hv.y);
            hhi.f = make_float2(hv.z, hv.w);
#pragma unroll
            for (int j = 0; j < 4; j++) {
                F2u wlo, whi;
                wlo.f = make_float2(wreg[j][c].x, wreg[j][c].y);
                whi.f = make_float2(wreg[j][c].z, wreg[j][c].w);
                fma2(acc[j], wlo.u, hlo.u);
                fma2(acc[j], whi.u, hhi.u);
            }
        }
#pragma unroll
        for (int j = 0; j < 4; j++) {
            F2u a; a.u = acc[j];
            float s = a.f.x + a.f.y;
#pragma unroll
            for (int off = 16; off; off >>= 1)
                s += __shfl_xor_sync(0xffffffffu, s, off);
            if (lane == 0) sh_z[wid * 4 + j] = s;
        }
        __syncthreads();

        // gates on threads 0..7; sh_z[u]=i, [8+u]=f, [16+u]=g, [24+u]=o
        if (tid < UNITS) {
            float zi = sh_z[tid]      + xzi;
            float zf = sh_z[8 + tid]  + xzf;
            float zg = sh_z[16 + tid] + xzg;
            float zo = sh_z[24 + tid] + xzo;
            float ig = fast_sigmoid(zi);
            float fg = fast_sigmoid(zf);
            float gg = fast_tanh(zg);
            float og = fast_sigmoid(zo);
            c_state  = fg * c_state + ig * gg;
            float h  = og * fast_tanh(c_state);
            sh_hout[tid] = h;
            g_hall[(size_t)t * H_DIM + ubase + tid] = h;  // consumed next launch
            __syncwarp(0x000000ffu);
            if (tid == 0) {
                float4 a = *(const float4*)&sh_hout[0];
                float4 b = *(const float4*)&sh_hout[4];
                __stcg((float4*)&g_h[t & 1][ubase], a);
                __stcg((float4*)&g_h[t & 1][ubase + 4], b);
                st_release_gpu(&g_flag[bid], base + t + 1);  // same-thread release orders stores
            }
        }
        // no trailing barrier: sh_h/sh_z/sh_hout overwrites at t+1 all occur
        // after at least one of the t+1 barriers above.
    }
}

// ---------------- final FC: out[t][o] = hall[t] . fcW[o] + fcb[o] ----------
__global__ void fc_kernel(const float* __restrict__ W,
                          const float* __restrict__ b,
                          float* __restrict__ out) {
    int t    = blockIdx.x;
    int o    = threadIdx.x >> 5;   // 10 warps
    int lane = threadIdx.x & 31;
    const float4* h = (const float4*)(g_hall + (size_t)t * H_DIM);
    const float4* w = (const float4*)(W + (size_t)o * H_DIM);
    float s = 0.f;
#pragma unroll
    for (int c = 0; c < 8; c++) {
        float4 hv = h[c * 32 + lane];
        float4 wv = w[c * 32 + lane];
        s += hv.x * wv.x + hv.y * wv.y + hv.z * wv.z + hv.w * wv.w;
    }
#pragma unroll
    for (int off = 16; off; off >>= 1)
        s += __shfl_xor_sync(0xffffffffu, s, off);
    if (lane == 0) out[t * 10 + o] = s + b[o];
}

// ---------------- launch ----------------------------------------------------
extern "C" void kernel_launch(void* const* d_in, const int* in_sizes, int n_in,
                              void* d_out, int out_size) {
    const float* x     = (const float*)d_in[0];
    const float* Wih0  = (const float*)d_in[1];
    const float* Whh0  = (const float*)d_in[2];
    const float* b0    = (const float*)d_in[3];
    const float* WihR  = (const float*)d_in[4];
    const float* WhhR  = (const float*)d_in[5];
    const float* bR    = (const float*)d_in[6];
    const float* fcW   = (const float*)d_in[7];
    const float* fcb   = (const float*)d_in[8];
    float*       out   = (float*)d_out;

    reset_kernel<<<1, 128>>>();

    dim3 ggrid(G4H / 128, T_LEN / 128);
    dim3 gblk(256);

    // layer 0
    gemm_xz<IN_DIM><<<ggrid, gblk>>>(x, Wih0, b0);
    lstm_scan<<<NCTA, 256>>>(Whh0, 0);

    // layers 1..3
    for (int l = 1; l < 4; l++) {
        const float* Wih = WihR + (size_t)(l - 1) * G4H * H_DIM;
        const float* Whh = WhhR + (size_t)(l - 1) * G4H * H_DIM;
        const float* bb  = bR   + (size_t)(l - 1) * G4H;
        gemm_xz<H_DIM><<<ggrid, gblk>>>(nullptr /* = g_hall */, Wih, bb);
        lstm_scan<<<NCTA, 256>>>(Whh, l);
    }

    fc_kernel<<<T_LEN, 320>>>(fcW, fcb, out);
}

// round 5
// speedup vs baseline: 2.3951x; 2.3951x over previous
#include <cuda_runtime.h>
#include <cstdint>

#define T_LEN 4096
#define IN_DIM 256
#define H_DIM 1024
#define G4H   4096
#define NCTA  128
#define UNITS 8     // hidden units per CTA (128 * 8 = 1024)

// ---------------- device scratch (static: no allocations allowed) ----------
__device__ float    g_xz[(size_t)T_LEN * G4H];     // 64 MB: input projections
__device__ float    g_hall[(size_t)T_LEN * H_DIM]; // 16 MB: h outputs of current layer
__device__ float    g_h[2][H_DIM];                 // double-buffered h broadcast
__device__ unsigned g_cnt[4];                      // per-layer arrival counters

__global__ void reset_kernel() {
    if (threadIdx.x < 4) g_cnt[threadIdx.x] = 0u;
}

// ---------------- memory-order helpers --------------------------------------
__device__ __forceinline__ void red_release_add(unsigned* p, unsigned v) {
    asm volatile("red.release.gpu.global.add.u32 [%0], %1;" :: "l"(p), "r"(v) : "memory");
}
__device__ __forceinline__ unsigned ld_relaxed_gpu(const unsigned* p) {
    unsigned v;
    asm volatile("ld.relaxed.gpu.global.u32 %0, [%1];" : "=r"(v) : "l"(p) : "memory");
    return v;
}
__device__ __forceinline__ unsigned ld_acquire_gpu(const unsigned* p) {
    unsigned v;
    asm volatile("ld.acquire.gpu.global.u32 %0, [%1];" : "=r"(v) : "l"(p) : "memory");
    return v;
}

// ---------------- packed f32x2 FMA helper ----------------------------------
union F2u { float2 f; unsigned long long u; };

__device__ __forceinline__ void fma2(unsigned long long& d,
                                     unsigned long long a,
                                     unsigned long long b) {
    asm volatile("fma.rn.f32x2 %0, %1, %2, %0;" : "+l"(d) : "l"(a), "l"(b));
}

// ---------------- fast, overflow-safe activations ---------------------------
__device__ __forceinline__ float fast_sigmoid(float x) {
    return __fdividef(1.f, 1.f + __expf(-x));
}
__device__ __forceinline__ float fast_tanh(float x) {
    float a = fabsf(x);
    float e = __expf(-2.f * a);               // in (0, 1], never overflows
    float t = (1.f - e) * __fdividef(1.f, 1.f + e);
    return copysignf(t, x);
}

// ---------------- GEMM: xz = A @ W^T + bias --------------------------------
template<int K>
__global__ __launch_bounds__(256, 2)
void gemm_xz(const float* __restrict__ A_in,
             const float* __restrict__ W,
             const float* __restrict__ bias) {
    const float* A = A_in ? A_in : g_hall;   // nullptr => previous layer's h

    __shared__ float As[16][132];
    __shared__ float Bs[16][132];

    const int tid  = threadIdx.x;
    const int row0 = blockIdx.y * 128;
    const int col0 = blockIdx.x * 128;
    const int ty   = tid >> 4;
    const int tx   = tid & 15;

    float acc[8][8];
#pragma unroll
    for (int i = 0; i < 8; i++)
#pragma unroll
        for (int j = 0; j < 8; j++) acc[i][j] = 0.f;

    for (int k0 = 0; k0 < K; k0 += 16) {
#pragma unroll
        for (int i = 0; i < 2; i++) {
            int f  = tid + i * 256;
            int r  = f >> 2;
            int c4 = f & 3;
            float4 va = *(const float4*)(A + (size_t)(row0 + r) * K + k0 + c4 * 4);
            As[c4 * 4 + 0][r] = va.x;
            As[c4 * 4 + 1][r] = va.y;
            As[c4 * 4 + 2][r] = va.z;
            As[c4 * 4 + 3][r] = va.w;
            float4 vb = *(const float4*)(W + (size_t)(col0 + r) * K + k0 + c4 * 4);
            Bs[c4 * 4 + 0][r] = vb.x;
            Bs[c4 * 4 + 1][r] = vb.y;
            Bs[c4 * 4 + 2][r] = vb.z;
            Bs[c4 * 4 + 3][r] = vb.w;
        }
        __syncthreads();

#pragma unroll
        for (int k = 0; k < 16; k++) {
            float4 a0 = *(const float4*)&As[k][ty * 8];
            float4 a1 = *(const float4*)&As[k][ty * 8 + 4];
            float4 b0 = *(const float4*)&Bs[k][tx * 8];
            float4 b1 = *(const float4*)&Bs[k][tx * 8 + 4];
            float a[8] = {a0.x, a0.y, a0.z, a0.w, a1.x, a1.y, a1.z, a1.w};
            float b[8] = {b0.x, b0.y, b0.z, b0.w, b1.x, b1.y, b1.z, b1.w};
#pragma unroll
            for (int i = 0; i < 8; i++)
#pragma unroll
                for (int j = 0; j < 8; j++) acc[i][j] += a[i] * b[j];
        }
        __syncthreads();
    }

    float bj[8];
#pragma unroll
    for (int j = 0; j < 8; j++) bj[j] = bias[col0 + tx * 8 + j];

#pragma unroll
    for (int i = 0; i < 8; i++) {
        int r = row0 + ty * 8 + i;
#pragma unroll
        for (int j = 0; j < 8; j++) {
            g_xz[(size_t)r * G4H + col0 + tx * 8 + j] = acc[i][j] + bj[j];
        }
    }
}

// ---------------- recurrent scan -------------------------------------------
// 128 CTAs x 256 threads, all co-resident. CTA b owns hidden units [8b, 8b+8).
// W_hh slice (32 rows x 1024) lives in REGISTERS (128 floats/thread).
// Sync fabric:
//   producer: 8 STG.cg of h slice -> __syncwarp -> lane0 red.release.gpu (+1)
//   consumer: tid 0 spins ld.relaxed on ONE counter, one ld.acquire at pickup;
//             everyone else sleeps at the barrier.
__global__ __launch_bounds__(256, 1)
void lstm_scan(const float* __restrict__ Whh, int layer) {
    __shared__ float sh_h[H_DIM];
    __shared__ float sh_z[32];

    const int bid   = blockIdx.x;
    const int tid   = threadIdx.x;
    const int wid   = tid >> 5;
    const int lane  = tid & 31;
    const int ubase = bid * UNITS;

    // load this CTA's W_hh slice into registers.
    // warp w handles slice-rows s = 4w..4w+3, s -> (gate = s>>3, unit = s&7).
    float4 wreg[4][8];
#pragma unroll
    for (int j = 0; j < 4; j++) {
        int s    = wid * 4 + j;
        int gate = s >> 3;
        int unit = s & 7;
        const float4* wr =
            (const float4*)(Whh + ((size_t)gate * H_DIM + ubase + unit) * H_DIM);
#pragma unroll
        for (int c = 0; c < 8; c++) wreg[j][c] = wr[c * 32 + lane];
    }

    unsigned* cnt = &g_cnt[layer];
    float c_state = 0.f;   // meaningful for tid < 8 only

    // init publish: h_{-1} = 0 lives in parity-1 buffer
    if (tid < UNITS) {
        __stcg(&g_h[1][ubase + tid], 0.f);
        __syncwarp(0x000000ffu);
        if (tid == 0) red_release_add(cnt, 1u);   // cnt reaches 128 => h_{-1} ready
    }

    for (int t = 0; t < T_LEN; t++) {
        // prefetch xz for this step (independent of h; overlaps the spin)
        float xzi = 0.f, xzf = 0.f, xzg = 0.f, xzo = 0.f;
        if (tid < UNITS) {
            const float* xz = g_xz + (size_t)t * G4H + ubase + tid;
            xzi = __ldg(xz);
            xzf = __ldg(xz + H_DIM);
            xzg = __ldg(xz + 2 * H_DIM);
            xzo = __ldg(xz + 3 * H_DIM);
        }

        // single poller; relaxed spin, single acquire at pickup
        if (tid == 0) {
            const unsigned target = (unsigned)NCTA * (unsigned)(t + 1);
            if (ld_relaxed_gpu(cnt) < target) {
                while (ld_relaxed_gpu(cnt) < target) { }
            }
            (void)ld_acquire_gpu(cnt);   // establish ordering once
        }
        __syncthreads();                                   // (A)

        // broadcast h_{t-1} into shared (256 x float4 = 4KB)
        {
            const float4* hp = (const float4*)g_h[(t + 1) & 1];
            ((float4*)sh_h)[tid] = __ldcg(hp + tid);
        }
        __syncthreads();                                   // (B)

        // packed dot products: 4 rows per warp, 32 cols per lane (conflict-free)
        unsigned long long acc[4];
        {
            F2u z; z.f = make_float2(0.f, 0.f);
            acc[0] = acc[1] = acc[2] = acc[3] = z.u;
        }
#pragma unroll
        for (int c = 0; c < 8; c++) {
            float4 hv = ((const float4*)sh_h)[c * 32 + lane];
            F2u hlo, hhi;
            hlo.f = make_float2(hv.x, hv.y);
            hhi.f = make_float2(hv.z, hv.w);
#pragma unroll
            for (int j = 0; j < 4; j++) {
                F2u wlo, whi;
                wlo.f = make_float2(wreg[j][c].x, wreg[j][c].y);
                whi.f = make_float2(wreg[j][c].z, wreg[j][c].w);
                fma2(acc[j], wlo.u, hlo.u);
                fma2(acc[j], whi.u, hhi.u);
            }
        }

        // 4 independent butterfly reductions, interleaved so the 5-deep SHFL
        // chains pipeline across the 4 values.
        float s0, s1, s2, s3;
        {
            F2u a0, a1, a2, a3;
            a0.u = acc[0]; a1.u = acc[1]; a2.u = acc[2]; a3.u = acc[3];
            s0 = a0.f.x + a0.f.y;
            s1 = a1.f.x + a1.f.y;
            s2 = a2.f.x + a2.f.y;
            s3 = a3.f.x + a3.f.y;
#pragma unroll
            for (int off = 16; off; off >>= 1) {
                s0 += __shfl_xor_sync(0xffffffffu, s0, off);
                s1 += __shfl_xor_sync(0xffffffffu, s1, off);
                s2 += __shfl_xor_sync(0xffffffffu, s2, off);
                s3 += __shfl_xor_sync(0xffffffffu, s3, off);
            }
        }
        if (lane == 0) {
            sh_z[wid * 4 + 0] = s0;
            sh_z[wid * 4 + 1] = s1;
            sh_z[wid * 4 + 2] = s2;
            sh_z[wid * 4 + 3] = s3;
        }
        __syncthreads();                                   // (C)

        // gates on threads 0..7; sh_z[u]=i, [8+u]=f, [16+u]=g, [24+u]=o
        if (tid < UNITS) {
            float zi = sh_z[tid]      + xzi;
            float zf = sh_z[8 + tid]  + xzf;
            float zg = sh_z[16 + tid] + xzg;
            float zo = sh_z[24 + tid] + xzo;
            float ig = fast_sigmoid(zi);
            float fg = fast_sigmoid(zf);
            float gg = fast_tanh(zg);
            float og = fast_sigmoid(zo);
            c_state  = fg * c_state + ig * gg;
            float h  = og * fast_tanh(c_state);
            __stcg(&g_h[t & 1][ubase + tid], h);           // publish data
            __syncwarp(0x000000ffu);
            if (tid == 0) red_release_add(cnt, 1u);        // publish flag (orders stores)
            g_hall[(size_t)t * H_DIM + ubase + tid] = h;   // off the release drain path
        }
        // no trailing barrier: the poller is lane 0 of THIS warp, so no lane can
        // reach the next spin before gates finish; smem overwrites at t+1 all sit
        // behind barrier (A)/(B) of t+1 which require warp 0 (post-gates) to arrive.
    }
}

// ---------------- final FC: out[t][o] = hall[t] . fcW[o] + fcb[o] ----------
__global__ void fc_kernel(const float* __restrict__ W,
                          const float* __restrict__ b,
                          float* __restrict__ out) {
    int t    = blockIdx.x;
    int o    = threadIdx.x >> 5;   // 10 warps
    int lane = threadIdx.x & 31;
    const float4* h = (const float4*)(g_hall + (size_t)t * H_DIM);
    const float4* w = (const float4*)(W + (size_t)o * H_DIM);
    float s = 0.f;
#pragma unroll
    for (int c = 0; c < 8; c++) {
        float4 hv = h[c * 32 + lane];
        float4 wv = w[c * 32 + lane];
        s += hv.x * wv.x + hv.y * wv.y + hv.z * wv.z + hv.w * wv.w;
    }
#pragma unroll
    for (int off = 16; off; off >>= 1)
        s += __shfl_xor_sync(0xffffffffu, s, off);
    if (lane == 0) out[t * 10 + o] = s + b[o];
}

// ---------------- launch ----------------------------------------------------
extern "C" void kernel_launch(void* const* d_in, const int* in_sizes, int n_in,
                              void* d_out, int out_size) {
    const float* x     = (const float*)d_in[0];
    const float* Wih0  = (const float*)d_in[1];
    const float* Whh0  = (const float*)d_in[2];
    const float* b0    = (const float*)d_in[3];
    const float* WihR  = (const float*)d_in[4];
    const float* WhhR  = (const float*)d_in[5];
    const float* bR    = (const float*)d_in[6];
    const float* fcW   = (const float*)d_in[7];
    const float* fcb   = (const float*)d_in[8];
    float*       out   = (float*)d_out;

    reset_kernel<<<1, 32>>>();

    dim3 ggrid(G4H / 128, T_LEN / 128);
    dim3 gblk(256);

    // layer 0
    gemm_xz<IN_DIM><<<ggrid, gblk>>>(x, Wih0, b0);
    lstm_scan<<<NCTA, 256>>>(Whh0, 0);

    // layers 1..3
    for (int l = 1; l < 4; l++) {
        const float* Wih = WihR + (size_t)(l - 1) * G4H * H_DIM;
        const float* Whh = WhhR + (size_t)(l - 1) * G4H * H_DIM;
        const float* bb  = bR   + (size_t)(l - 1) * G4H;
        gemm_xz<H_DIM><<<ggrid, gblk>>>(nullptr /* = g_hall */, Wih, bb);
        lstm_scan<<<NCTA, 256>>>(Whh, l);
    }

    fc_kernel<<<T_LEN, 320>>>(fcW, fcb, out);
}